// round 7
// baseline (speedup 1.0000x reference)
#include <cuda_runtime.h>
#include <cuda_bf16.h>
#include <cuda_pipeline.h>
#include <limits.h>

// StreamingRhythmProjector on GB300 — v6: persistent CTAs + cp.async
// double-buffered row pipeline.
//
// v5 lesson: with only 4 loads/thread before the reduction barrier, each CTA
// exposes ~load-latency at every barrier and DRAM sits at 50%. v6 keeps DRAM
// busy during the barrier-heavy phase of row k by streaming row k+1's four
// input streams into the alternate smem buffer with cp.async (LDGSTS).
//
// Output (f32 flat): speech[B*U] | pause[B*U] | effective[B*U] |
//                    commit[B] | next_phase[B] | next_backlog[B] | next_clock[B]

#define BS 512
#define NW (BS / 32)
#define U_MAX 2048
#define MAX_ROWS 65536

__device__ static int g_visible[MAX_ROWS];
__device__ static int g_first[MAX_ROWS];

__device__ __forceinline__ float warpSum(float v) {
    #pragma unroll
    for (int o = 16; o > 0; o >>= 1) v += __shfl_down_sync(0xffffffffu, v, o);
    return v;
}
__device__ __forceinline__ int warpMin(int v) {
    #pragma unroll
    for (int o = 16; o > 0; o >>= 1) v = min(v, __shfl_down_sync(0xffffffffu, v, o));
    return v;
}

// ---------------------------------------------------------------------------
// Pre-kernel: one warp per row -> g_visible (prefix binary search) and
// g_first (first open index in visible prefix). Latency chains overlap
// across all 4096 rows.
// ---------------------------------------------------------------------------
__global__ __launch_bounds__(256)
void precompute_row_stats(const float* __restrict__ unit_mask,
                          const int*   __restrict__ open_run,
                          int B, int U)
{
    const int warp = blockIdx.x * (blockDim.x >> 5) + (threadIdx.x >> 5);
    const int lane = threadIdx.x & 31;
    if (warp >= B) return;
    const size_t base = (size_t)warp * (size_t)U;

    int lo = 0, hi = U;
    while (hi > lo) {
        const int step = (hi - lo + 31) >> 5;
        const int p = lo + lane * step;
        bool one = false;
        if (p < hi) one = (__ldg(unit_mask + base + p) > 0.5f);
        const unsigned ball = __ballot_sync(0xffffffffu, one);
        const int n1 = __popc(ball);
        if (n1 == 0) {
            hi = lo;
        } else {
            const int nl = lo + (n1 - 1) * step + 1;
            const int f0 = lo + n1 * step;
            hi = (f0 < hi) ? f0 : hi;
            lo = nl;
        }
    }
    const int visible = lo;

    int fo = INT_MAX;
    for (int start = 0; start < visible; start += 128) {
        const int idx = start + lane * 4;
        int m = INT_MAX;
        if (idx < U) {
            if (idx + 3 < U) {
                const int4 v = __ldg((const int4*)(open_run + base + idx));
                if (v.x > 0 && idx + 0 < visible) m = min(m, idx + 0);
                if (v.y > 0 && idx + 1 < visible) m = min(m, idx + 1);
                if (v.z > 0 && idx + 2 < visible) m = min(m, idx + 2);
                if (v.w > 0 && idx + 3 < visible) m = min(m, idx + 3);
            } else {
                for (int e = 0; e < 4 && idx + e < U; e++)
                    if (idx + e < visible && __ldg(open_run + base + idx + e) > 0)
                        m = min(m, idx + e);
            }
        }
        const int wm = warpMin(m);
        const int bwm = __shfl_sync(0xffffffffu, wm, 0);
        if (bwm != INT_MAX) { fo = bwm; break; }
    }

    if (lane == 0) {
        g_visible[warp] = visible;
        g_first[warp]   = fo;
    }
}

// ---------------------------------------------------------------------------
// Main kernel: persistent CTAs, grid-stride over rows, cp.async double buffer.
// Requires U % 4 == 0 and U <= U_MAX.
// Dynamic smem: 2 buffers x 4 streams x U_MAX floats = 64 KB.
// ---------------------------------------------------------------------------
__global__ __launch_bounds__(BS, 3)
void rhythm_projector_v6(
    const float* __restrict__ anchor_src,
    const float* __restrict__ speech_budget,
    const float* __restrict__ pause_budget,
    const float* __restrict__ lr_unit,
    const float* __restrict__ pw_unit,
    const float* __restrict__ bl_unit,
    const float* __restrict__ phase_ptr,
    const float* __restrict__ backlog,
    const float* __restrict__ clock_delta,
    const int*   __restrict__ commit_frontier,
    float* __restrict__ out,
    int B, int U)
{
    extern __shared__ float sbuf[];   // [2][4][U_MAX]
    __shared__ float s_f0[NW], s_f1[NW], s_f2[NW];
    __shared__ float s_bcast[2];

    const int tid = threadIdx.x;
    const size_t BU = (size_t)B * (size_t)U;
    const int j = tid * 4;
    const bool in = (j < U);
    const int byteOff = j * 4;            // byte offset of this thread's chunk
    const bool copies = (byteOff < U * 4);

    // -------- prefetch helper (one 16B chunk per thread per stream) ---------
    #define PREFETCH_ROW(bufp, row)                                              \
    {                                                                            \
        if (copies) {                                                            \
            const size_t rb = (size_t)(row) * (size_t)U + (size_t)j;             \
            __pipeline_memcpy_async((bufp) + 0 * U_MAX + j, anchor_src + rb, 16);\
            __pipeline_memcpy_async((bufp) + 1 * U_MAX + j, lr_unit    + rb, 16);\
            __pipeline_memcpy_async((bufp) + 2 * U_MAX + j, pw_unit    + rb, 16);\
            __pipeline_memcpy_async((bufp) + 3 * U_MAX + j, bl_unit    + rb, 16);\
        }                                                                        \
        __pipeline_commit();                                                     \
    }

    int row  = blockIdx.x;
    if (row >= B) return;
    int pbuf = 0;
    PREFETCH_ROW(sbuf, row)

    while (row < B) {
        const int next = row + gridDim.x;
        if (next < B) {
            PREFETCH_ROW(sbuf + (pbuf ^ 1) * 4 * U_MAX, next)
            __pipeline_wait_prior(1);
        } else {
            __pipeline_wait_prior(0);
        }

        // ================== process `row` from buffer pbuf ==================
        const float* s_ar = sbuf + pbuf * 4 * U_MAX + 0 * U_MAX;
        const float* s_lr = sbuf + pbuf * 4 * U_MAX + 1 * U_MAX;
        const float* s_pw = sbuf + pbuf * 4 * U_MAX + 2 * U_MAX;
        const float* s_bl = sbuf + pbuf * 4 * U_MAX + 3 * U_MAX;

        const size_t base = (size_t)row * (size_t)U;
        const int visible    = g_visible[row];
        const int first_open = g_first[row];

        // ---- Pass A: compute sp/sc (kept in regs across barrier) + sums ----
        float4 ar = make_float4(0.f, 0.f, 0.f, 0.f);
        float4 spv = ar, scv = ar;
        float sum_sp = 0.f, sum_sc = 0.f;
        if (in) {
            ar              = *(const float4*)(s_ar + j);
            const float4 lr = *(const float4*)(s_lr + j);
            const float4 pw = *(const float4*)(s_pw + j);
            const float4 bl = *(const float4*)(s_bl + j);

            #define ELEM(c, e)                                                    \
            {                                                                     \
                if ((j + e) < visible) {                                          \
                    const float a  = fmaxf(ar.c, 1.0f);                           \
                    const float bb = a * __expf(lr.c);                            \
                    spv.c = fmaxf(fminf(bb, a * 3.0f), 1.0f);                     \
                    scv.c = fmaxf(pw.c, 0.f) * (0.5f + bl.c);                     \
                }                                                                 \
            }
            ELEM(x, 0) ELEM(y, 1) ELEM(z, 2) ELEM(w, 3)
            #undef ELEM
            sum_sp = (spv.x + spv.y) + (spv.z + spv.w);
            sum_sc = (scv.x + scv.y) + (scv.z + scv.w);
        }

        // ---- block reduction (sum_sp, sum_sc) ----
        {
            float w0 = warpSum(sum_sp);
            float w1 = warpSum(sum_sc);
            const int wid = tid >> 5, lid = tid & 31;
            __syncthreads();   // protect s_f* reuse from previous row
            if (lid == 0) { s_f0[wid] = w0; s_f1[wid] = w1; }
            __syncthreads();
            if (wid == 0) {
                float v0 = (lid < NW) ? s_f0[lid] : 0.f;
                float v1 = (lid < NW) ? s_f1[lid] : 0.f;
                #pragma unroll
                for (int o = 8; o > 0; o >>= 1) {
                    v0 += __shfl_down_sync(0xffffffffu, v0, o);
                    v1 += __shfl_down_sync(0xffffffffu, v1, o);
                }
                if (lid == 0) { s_bcast[0] = v0; s_bcast[1] = v1; }
            }
            __syncthreads();
            sum_sp = s_bcast[0]; sum_sc = s_bcast[1];
        }

        // ---- scalar frontier logic (uniform across block) ----
        const float sbud = speech_budget[row];
        const float pbud = pause_budget[row];
        const float speech_scale = sbud / fmaxf(sum_sp, 1e-6f);

        const bool has_open = (first_open != INT_MAX);
        const int  closed   = has_open ? first_open : visible;
        const int  cap      = max(visible - 2, 0);    // TAIL_HOLD_UNITS
        int cand = min(cap, closed);
        const int prev = commit_frontier[row];
        const int bidx = min(max(cand - 1, 0), U - 1);
        const float bval = s_bl[bidx];                // uniform smem broadcast
        const bool soft = (cand > 0) && (cand < visible) && (bval < 0.45f);
        if (soft) cand = max(prev, cand - 1);
        const int commit = max(prev, cand);

        const bool  use_scores = (sum_sc > 0.f);
        const float wdenom = pbud / fmaxf(sum_sc, 1e-6f);
        const float fb     = pbud / fmaxf((float)visible, 1.f);

        // ---- Pass B: outputs + window sums ----
        float sum_eff = 0.f, exec_s = 0.f, src_s = 0.f;
        if (in) {
            float4 speech, pause, eff;
            // prefix mask: speech/pause already zero beyond visible;
            // effective = speech + pause exactly (m in {0,1}).
            #define ELEM(c, e)                                                 \
            {                                                                  \
                speech.c = spv.c * speech_scale;                               \
                pause.c = use_scores ? (scv.c * wdenom)                        \
                                     : (((j + e) < visible) ? fb : 0.f);       \
                eff.c = speech.c + pause.c;                                    \
                sum_eff += eff.c;                                              \
                const int je = j + e;                                          \
                if (je >= prev && je < commit) {                               \
                    exec_s += eff.c;                                           \
                    src_s  += ar.c;                                            \
                }                                                              \
            }
            ELEM(x, 0) ELEM(y, 1) ELEM(z, 2) ELEM(w, 3)
            #undef ELEM

            __stcs((float4*)(out + base + j),          speech);
            __stcs((float4*)(out + BU + base + j),     pause);
            __stcs((float4*)(out + 2 * BU + base + j), eff);
        }

        // ---- final 3-way reduction + tail outputs ----
        {
            float w0 = warpSum(sum_eff);
            float w1 = warpSum(exec_s);
            float w2 = warpSum(src_s);
            const int wid = tid >> 5, lid = tid & 31;
            __syncthreads();   // protect s_f* reuse
            if (lid == 0) { s_f0[wid] = w0; s_f1[wid] = w1; s_f2[wid] = w2; }
            __syncthreads();
            if (tid == 0) {
                float v0 = 0.f, v1 = 0.f, v2 = 0.f;
                #pragma unroll
                for (int i = 0; i < NW; i++) { v0 += s_f0[i]; v1 += s_f1[i]; v2 += s_f2[i]; }

                const bool adv = commit > prev;
                const float cd = clock_delta[row];
                const float next_clock = adv ? (cd + (v1 - v2)) : cd;
                const float next_backlog = adv ? fmaxf(next_clock, 0.f) : backlog[row];
                const float vt = fmaxf(v0, 1.f);
                float next_phase = phase_ptr[row];
                if (adv) next_phase = fminf(fmaxf(next_phase + v1 / vt, 0.f), 1.f);

                float* tail = out + 3 * BU;
                tail[row]         = (float)commit;
                tail[B + row]     = next_phase;
                tail[2 * B + row] = next_backlog;
                tail[3 * B + row] = next_clock;
            }
        }

        row = next;
        pbuf ^= 1;
    }
    #undef PREFETCH_ROW
}

// ---------------------------------------------------------------------------
// Scalar fallback kernel (any shape; self-contained, no prefix assumption)
// ---------------------------------------------------------------------------
template<int ITEMS>
__global__ __launch_bounds__(BS)
void rhythm_projector_scalar(
    const float* __restrict__ anchor_src,
    const float* __restrict__ unit_mask,
    const float* __restrict__ speech_budget,
    const float* __restrict__ pause_budget,
    const float* __restrict__ lr_unit,
    const float* __restrict__ pw_unit,
    const float* __restrict__ bl_unit,
    const float* __restrict__ phase_ptr,
    const float* __restrict__ backlog,
    const float* __restrict__ clock_delta,
    const int*   __restrict__ commit_frontier,
    const int*   __restrict__ open_run,
    float* __restrict__ out,
    int B, int U)
{
    const int row = blockIdx.x;
    const int tid = threadIdx.x;
    const size_t base = (size_t)row * (size_t)U;
    const size_t BU = (size_t)B * (size_t)U;

    __shared__ float s_f0[NW], s_f1[NW], s_f2[NW];
    __shared__ int   s_i0[NW];
    __shared__ float s_bcast[3];
    __shared__ int   s_ibcast;

    float sp[ITEMS], sc[ITEMS], msk[ITEMS];
    float sum_sp = 0.f, sum_sc = 0.f, sum_m = 0.f;
    int first_open = INT_MAX;

    #pragma unroll
    for (int k = 0; k < ITEMS; k++) {
        const int j = k * BS + tid;
        float m = 0.f, spv = 0.f, scv = 0.f;
        if (j < U) {
            const float arv = anchor_src[base + j];
            m               = unit_mask[base + j];
            const float lrv = lr_unit[base + j];
            const float pwv = pw_unit[base + j];
            const float blv = bl_unit[base + j];
            const int   opv = open_run[base + j];
            const float a   = fmaxf(arv, 1.0f);
            const float b   = a * __expf(lrv);
            spv = fmaxf(fminf(b, a * 3.0f), 1.0f) * m;
            scv = fmaxf(pwv, 0.f) * (0.5f + blv) * m;
            if (opv > 0 && m > 0.f) first_open = min(first_open, j);
        }
        sp[k] = spv; sc[k] = scv; msk[k] = m;
        sum_sp += spv; sum_sc += scv; sum_m += m;
    }

    {
        float w0 = warpSum(sum_sp), w1 = warpSum(sum_sc), w2 = warpSum(sum_m);
        int w3 = warpMin(first_open);
        const int wid = tid >> 5, lid = tid & 31;
        if (lid == 0) { s_f0[wid] = w0; s_f1[wid] = w1; s_f2[wid] = w2; s_i0[wid] = w3; }
        __syncthreads();
        if (wid == 0) {
            float v0 = (lid < NW) ? s_f0[lid] : 0.f;
            float v1 = (lid < NW) ? s_f1[lid] : 0.f;
            float v2 = (lid < NW) ? s_f2[lid] : 0.f;
            int   v3 = (lid < NW) ? s_i0[lid] : INT_MAX;
            #pragma unroll
            for (int o = 8; o > 0; o >>= 1) {
                v0 += __shfl_down_sync(0xffffffffu, v0, o);
                v1 += __shfl_down_sync(0xffffffffu, v1, o);
                v2 += __shfl_down_sync(0xffffffffu, v2, o);
                v3 = min(v3, __shfl_down_sync(0xffffffffu, v3, o));
            }
            if (lid == 0) { s_bcast[0] = v0; s_bcast[1] = v1; s_bcast[2] = v2; s_ibcast = v3; }
        }
        __syncthreads();
        sum_sp = s_bcast[0]; sum_sc = s_bcast[1]; sum_m = s_bcast[2];
        first_open = s_ibcast;
    }

    const float sbud = speech_budget[row];
    const float pbud = pause_budget[row];
    const float speech_scale = sbud / fmaxf(sum_sp, 1e-6f);
    const int  visible  = (int)sum_m;
    const bool has_open = (first_open != INT_MAX);
    const int  closed   = has_open ? first_open : visible;
    const int  cap      = max(visible - 2, 0);
    int cand = min(cap, closed);
    const int prev = commit_frontier[row];
    const int bidx = min(max(cand - 1, 0), U - 1);
    const float bval = __ldg(bl_unit + base + bidx);
    const bool soft = (cand > 0) && (cand < visible) && (bval < 0.45f);
    if (soft) cand = max(prev, cand - 1);
    const int commit = max(prev, cand);

    const bool  use_scores = (sum_sc > 0.f);
    const float wdenom = 1.f / fmaxf(sum_sc, 1e-6f);
    const float fb     = 1.f / fmaxf(sum_m, 1.f);

    float sum_eff = 0.f, exec_s = 0.f, src_s = 0.f;
    #pragma unroll
    for (int k = 0; k < ITEMS; k++) {
        const int j = k * BS + tid;
        if (j < U) {
            const float speech = sp[k] * speech_scale;
            const float w      = use_scores ? (sc[k] * wdenom) : (msk[k] * fb);
            const float pause  = w * pbud;
            const float eff    = (speech + pause) * msk[k];
            out[base + j]          = speech;
            out[BU + base + j]     = pause;
            out[2 * BU + base + j] = eff;
            sum_eff += eff;
            if (j >= prev && j < commit) {
                exec_s += eff;
                src_s  += __ldg(anchor_src + base + j);
            }
        }
    }

    {
        float w0 = warpSum(sum_eff), w1 = warpSum(exec_s), w2 = warpSum(src_s);
        const int wid = tid >> 5, lid = tid & 31;
        if (lid == 0) { s_f0[wid] = w0; s_f1[wid] = w1; s_f2[wid] = w2; }
        __syncthreads();
        if (tid == 0) {
            float v0 = 0.f, v1 = 0.f, v2 = 0.f;
            #pragma unroll
            for (int i = 0; i < NW; i++) { v0 += s_f0[i]; v1 += s_f1[i]; v2 += s_f2[i]; }
            const bool adv = commit > prev;
            const float cd = clock_delta[row];
            const float next_clock = adv ? (cd + (v1 - v2)) : cd;
            const float next_backlog = adv ? fmaxf(next_clock, 0.f) : backlog[row];
            const float vt = fmaxf(v0, 1.f);
            float next_phase = phase_ptr[row];
            if (adv) next_phase = fminf(fmaxf(next_phase + v1 / vt, 0.f), 1.f);
            float* tail = out + 3 * BU;
            tail[row]         = (float)commit;
            tail[B + row]     = next_phase;
            tail[2 * B + row] = next_backlog;
            tail[3 * B + row] = next_clock;
        }
    }
}

extern "C" void kernel_launch(void* const* d_in, const int* in_sizes, int n_in,
                              void* d_out, int out_size)
{
    const float* anchor_src  = (const float*)d_in[0];
    const float* unit_mask   = (const float*)d_in[1];
    const float* sbud        = (const float*)d_in[2];
    const float* pbud        = (const float*)d_in[3];
    const float* lr_unit     = (const float*)d_in[4];
    const float* pw_unit     = (const float*)d_in[5];
    const float* bl_unit     = (const float*)d_in[6];
    const float* phase_ptr   = (const float*)d_in[7];
    const float* backlog     = (const float*)d_in[8];
    const float* clock_delta = (const float*)d_in[9];
    const int*   frontier    = (const int*)d_in[10];
    const int*   open_run    = (const int*)d_in[11];
    float* out = (float*)d_out;

    const int B = in_sizes[2];            // speech_budget_win has B elements
    const int U = in_sizes[0] / B;        // dur_anchor_src has B*U

    if ((U & 3) == 0 && U <= U_MAX && B <= MAX_ROWS) {
        const size_t smemBytes = 2 * 4 * U_MAX * sizeof(float);   // 64 KB
        static bool attr_set = false;
        if (!attr_set) {
            cudaFuncSetAttribute(rhythm_projector_v6,
                                 cudaFuncAttributeMaxDynamicSharedMemorySize,
                                 (int)smemBytes);
            attr_set = true;
        }
        const int preBlocks = (B + 7) / 8;        // 8 warps / 256-thread block
        precompute_row_stats<<<preBlocks, 256>>>(unit_mask, open_run, B, U);

        const int nCTA = (B < 456) ? B : 456;     // ~3 CTAs/SM persistent
        rhythm_projector_v6<<<nCTA, BS, smemBytes>>>(anchor_src, sbud, pbud,
            lr_unit, pw_unit, bl_unit, phase_ptr, backlog, clock_delta, frontier,
            out, B, U);
    } else {
        const int items = (U + BS - 1) / BS;
        dim3 grid(B), block(BS);
        #define LAUNCH(N) rhythm_projector_scalar<N><<<grid, block>>>(anchor_src,    \
            unit_mask, sbud, pbud, lr_unit, pw_unit, bl_unit, phase_ptr, backlog,    \
            clock_delta, frontier, open_run, out, B, U)
        if      (items <= 4)  LAUNCH(4);
        else if (items <= 8)  LAUNCH(8);
        else if (items <= 16) LAUNCH(16);
        else                  LAUNCH(32);
        #undef LAUNCH
    }
}

// round 8
// speedup vs baseline: 1.3642x; 1.3642x over previous
#include <cuda_runtime.h>
#include <cuda_bf16.h>
#include <limits.h>

// StreamingRhythmProjector on GB300 — v7: single-barrier streaming kernel.
//
// v6 lesson: cp.async smem staging added L1 traffic + regs and regressed.
// v5 analysis: MLP was sufficient; the cost is the per-CTA critical path
// (two block barriers + serial reduce->compute->reduce chain) x 7 waves.
//
// v7 moves ALL frontier logic (visible, first_open, bval probe, commit,
// window anchor-sum) into the tiny pre-kernel, and folds the commit-window
// sums into the pass-A reduction. Main kernel: 4 loads -> elementwise ->
// ONE reduction -> compute + 3 stores. effective.sum is analytic (sbud+pbud).
//
// Output (f32 flat): speech[B*U] | pause[B*U] | effective[B*U] |
//                    commit[B] | next_phase[B] | next_backlog[B] | next_clock[B]

#define BS 512
#define NW (BS / 32)
#define MAX_ROWS 65536

__device__ static int   g_visible[MAX_ROWS];
__device__ static int   g_commit[MAX_ROWS];
__device__ static float g_srcsum[MAX_ROWS];

__device__ __forceinline__ float warpSum(float v) {
    #pragma unroll
    for (int o = 16; o > 0; o >>= 1) v += __shfl_down_sync(0xffffffffu, v, o);
    return v;
}
__device__ __forceinline__ int warpMin(int v) {
    #pragma unroll
    for (int o = 16; o > 0; o >>= 1) v = min(v, __shfl_down_sync(0xffffffffu, v, o));
    return v;
}

// ---------------------------------------------------------------------------
// Pre-kernel: one warp per row. Computes visible (prefix binary search),
// first_open (chunked scan), then the full commit-frontier logic and the
// window anchor sum src_s = sum anchor[prev..commit). All rows' dependent
// latency chains overlap across the grid (~5 round trips, ~2us total).
// ---------------------------------------------------------------------------
__global__ __launch_bounds__(256)
void precompute_row_stats(const float* __restrict__ unit_mask,
                          const int*   __restrict__ open_run,
                          const float* __restrict__ anchor_src,
                          const float* __restrict__ bl_unit,
                          const int*   __restrict__ commit_frontier,
                          int B, int U)
{
    const int warp = blockIdx.x * (blockDim.x >> 5) + (threadIdx.x >> 5);
    const int lane = threadIdx.x & 31;
    if (warp >= B) return;
    const size_t base = (size_t)warp * (size_t)U;

    // ---- binary search for prefix length (mask monotone 1..1 0..0) ----
    int lo = 0, hi = U;
    while (hi > lo) {
        const int step = (hi - lo + 31) >> 5;
        const int p = lo + lane * step;
        bool one = false;
        if (p < hi) one = (__ldg(unit_mask + base + p) > 0.5f);
        const unsigned ball = __ballot_sync(0xffffffffu, one);
        const int n1 = __popc(ball);
        if (n1 == 0) {
            hi = lo;
        } else {
            const int nl = lo + (n1 - 1) * step + 1;
            const int f0 = lo + n1 * step;
            hi = (f0 < hi) ? f0 : hi;
            lo = nl;
        }
    }
    const int visible = lo;

    // ---- first open index within visible prefix (128-elem chunks) ----
    int fo = INT_MAX;
    for (int start = 0; start < visible; start += 128) {
        const int idx = start + lane * 4;
        int m = INT_MAX;
        if (idx < U) {
            if (idx + 3 < U) {
                const int4 v = __ldg((const int4*)(open_run + base + idx));
                if (v.x > 0 && idx + 0 < visible) m = min(m, idx + 0);
                if (v.y > 0 && idx + 1 < visible) m = min(m, idx + 1);
                if (v.z > 0 && idx + 2 < visible) m = min(m, idx + 2);
                if (v.w > 0 && idx + 3 < visible) m = min(m, idx + 3);
            } else {
                for (int e = 0; e < 4 && idx + e < U; e++)
                    if (idx + e < visible && __ldg(open_run + base + idx + e) > 0)
                        m = min(m, idx + e);
            }
        }
        const int wm = warpMin(m);
        const int bwm = __shfl_sync(0xffffffffu, wm, 0);
        if (bwm != INT_MAX) { fo = bwm; break; }
    }

    // ---- commit frontier logic (uniform across warp) ----
    const bool has_open = (fo != INT_MAX);
    const int  closed   = has_open ? fo : visible;
    const int  cap      = max(visible - 2, 0);     // TAIL_HOLD_UNITS
    int cand = min(cap, closed);
    const int prev = __ldg(commit_frontier + warp);
    const int bidx = min(max(cand - 1, 0), U - 1);
    const float bval = __ldg(bl_unit + base + bidx);
    const bool soft = (cand > 0) && (cand < visible) && (bval < 0.45f);
    if (soft) cand = max(prev, cand - 1);
    const int commit = max(prev, cand);

    // ---- window anchor sum: src_s = sum anchor[prev .. commit) ----
    float s = 0.f;
    for (int p = prev + lane; p < commit; p += 32)
        s += __ldg(anchor_src + base + p);
    s = warpSum(s);

    if (lane == 0) {
        g_visible[warp] = visible;
        g_commit[warp]  = commit;
        g_srcsum[warp]  = s;
    }
}

// ---------------------------------------------------------------------------
// Main streaming kernel: ONE reduction barrier. U % 4 == 0, U <= BS*4.
// ---------------------------------------------------------------------------
__global__ __launch_bounds__(BS, 4)
void rhythm_projector_v7(
    const float* __restrict__ anchor_src,
    const float* __restrict__ speech_budget,
    const float* __restrict__ pause_budget,
    const float* __restrict__ lr_unit,
    const float* __restrict__ pw_unit,
    const float* __restrict__ bl_unit,
    const float* __restrict__ phase_ptr,
    const float* __restrict__ backlog,
    const float* __restrict__ clock_delta,
    const int*   __restrict__ commit_frontier,
    float* __restrict__ out,
    int B, int U)
{
    const int row = blockIdx.x;
    const int tid = threadIdx.x;
    const size_t base = (size_t)row * (size_t)U;
    const size_t BU = (size_t)B * (size_t)U;

    __shared__ float s_f0[NW], s_f1[NW], s_f2[NW], s_f3[NW];
    __shared__ float s_bcast[4];

    const int visible = g_visible[row];
    const int commit  = g_commit[row];
    const int prev    = commit_frontier[row];

    const int j = tid * 4;
    const bool in = (j < U);

    // -------- Pass A: load + elementwise + all partial sums -----------------
    float4 spv = make_float4(0.f, 0.f, 0.f, 0.f);
    float4 scv = spv;
    float sum_sp = 0.f, sum_sc = 0.f, win_sp = 0.f, win_sc = 0.f;
    if (in) {
        const float4 ar = __ldcs((const float4*)(anchor_src + base + j));
        const float4 lr = __ldcs((const float4*)(lr_unit    + base + j));
        const float4 pw = __ldcs((const float4*)(pw_unit    + base + j));
        const float4 bl = __ldcs((const float4*)(bl_unit    + base + j));

        #define ELEM(c, e)                                                    \
        {                                                                     \
            const int je = j + e;                                             \
            if (je < visible) {                                               \
                const float a  = fmaxf(ar.c, 1.0f);                           \
                const float bb = a * __expf(lr.c);                            \
                spv.c = fmaxf(fminf(bb, a * 3.0f), 1.0f);                     \
                scv.c = fmaxf(pw.c, 0.f) * (0.5f + bl.c);                     \
                if (je >= prev && je < commit) {                              \
                    win_sp += spv.c;                                          \
                    win_sc += scv.c;                                          \
                }                                                             \
            }                                                                 \
        }
        ELEM(x, 0) ELEM(y, 1) ELEM(z, 2) ELEM(w, 3)
        #undef ELEM
        sum_sp = (spv.x + spv.y) + (spv.z + spv.w);
        sum_sc = (scv.x + scv.y) + (scv.z + scv.w);
    }

    // -------- single block reduction (4 floats) -----------------------------
    {
        float w0 = warpSum(sum_sp);
        float w1 = warpSum(sum_sc);
        float w2 = warpSum(win_sp);
        float w3 = warpSum(win_sc);
        const int wid = tid >> 5, lid = tid & 31;
        if (lid == 0) { s_f0[wid] = w0; s_f1[wid] = w1; s_f2[wid] = w2; s_f3[wid] = w3; }
        __syncthreads();
        if (wid == 0) {
            float v0 = (lid < NW) ? s_f0[lid] : 0.f;
            float v1 = (lid < NW) ? s_f1[lid] : 0.f;
            float v2 = (lid < NW) ? s_f2[lid] : 0.f;
            float v3 = (lid < NW) ? s_f3[lid] : 0.f;
            #pragma unroll
            for (int o = 8; o > 0; o >>= 1) {
                v0 += __shfl_down_sync(0xffffffffu, v0, o);
                v1 += __shfl_down_sync(0xffffffffu, v1, o);
                v2 += __shfl_down_sync(0xffffffffu, v2, o);
                v3 += __shfl_down_sync(0xffffffffu, v3, o);
            }
            if (lid == 0) { s_bcast[0] = v0; s_bcast[1] = v1; s_bcast[2] = v2; s_bcast[3] = v3; }
        }
        __syncthreads();
        sum_sp = s_bcast[0]; sum_sc = s_bcast[1];
        win_sp = s_bcast[2]; win_sc = s_bcast[3];
    }

    // -------- scalar logic (uniform across block) ---------------------------
    const float sbud = speech_budget[row];
    const float pbud = pause_budget[row];
    const float speech_scale = sbud / fmaxf(sum_sp, 1e-6f);
    const bool  use_scores = (sum_sc > 0.f);
    const float wdenom = pbud / fmaxf(sum_sc, 1e-6f);
    const float fb     = pbud / fmaxf((float)visible, 1.f);

    // -------- Pass B: compute + 3 streaming stores (no reduction!) ----------
    if (in) {
        float4 speech, pause, eff;
        // prefix mask: spv/scv already zero beyond visible; eff = speech+pause
        // exactly since m in {0,1}.
        #define ELEM(c, e)                                                 \
        {                                                                  \
            speech.c = spv.c * speech_scale;                               \
            pause.c = use_scores ? (scv.c * wdenom)                        \
                                 : (((j + e) < visible) ? fb : 0.f);       \
            eff.c = speech.c + pause.c;                                    \
        }
        ELEM(x, 0) ELEM(y, 1) ELEM(z, 2) ELEM(w, 3)
        #undef ELEM

        __stcs((float4*)(out + base + j),          speech);
        __stcs((float4*)(out + BU + base + j),     pause);
        __stcs((float4*)(out + 2 * BU + base + j), eff);
    }

    // -------- tail outputs (thread 0, no further reduction needed) ----------
    if (tid == 0) {
        // exec_s = sum of effective over [prev, commit):
        //   speech part: speech_scale * win_sp
        //   pause part : use_scores ? wdenom * win_sc : fb * (commit - prev)
        const float exec_s = speech_scale * win_sp +
                             (use_scores ? (wdenom * win_sc)
                                         : (fb * (float)(commit - prev)));
        const float src_s = g_srcsum[row];

        const bool adv = commit > prev;
        const float cd = clock_delta[row];
        const float next_clock = adv ? (cd + (exec_s - src_s)) : cd;
        const float next_backlog = adv ? fmaxf(next_clock, 0.f) : backlog[row];
        // effective.sum == sbud + pbud analytically (speech renormalized to
        // its budget; pause weights sum to 1). Only consumed when adv.
        const float vt = fmaxf(sbud + pbud, 1.f);
        float next_phase = phase_ptr[row];
        if (adv) next_phase = fminf(fmaxf(next_phase + exec_s / vt, 0.f), 1.f);

        float* tail = out + 3 * BU;
        tail[row]         = (float)commit;
        tail[B + row]     = next_phase;
        tail[2 * B + row] = next_backlog;
        tail[3 * B + row] = next_clock;
    }
}

// ---------------------------------------------------------------------------
// Scalar fallback kernel (any shape; self-contained, no prefix assumption)
// ---------------------------------------------------------------------------
template<int ITEMS>
__global__ __launch_bounds__(BS)
void rhythm_projector_scalar(
    const float* __restrict__ anchor_src,
    const float* __restrict__ unit_mask,
    const float* __restrict__ speech_budget,
    const float* __restrict__ pause_budget,
    const float* __restrict__ lr_unit,
    const float* __restrict__ pw_unit,
    const float* __restrict__ bl_unit,
    const float* __restrict__ phase_ptr,
    const float* __restrict__ backlog,
    const float* __restrict__ clock_delta,
    const int*   __restrict__ commit_frontier,
    const int*   __restrict__ open_run,
    float* __restrict__ out,
    int B, int U)
{
    const int row = blockIdx.x;
    const int tid = threadIdx.x;
    const size_t base = (size_t)row * (size_t)U;
    const size_t BU = (size_t)B * (size_t)U;

    __shared__ float s_f0[NW], s_f1[NW], s_f2[NW];
    __shared__ int   s_i0[NW];
    __shared__ float s_bcast[3];
    __shared__ int   s_ibcast;

    float sp[ITEMS], sc[ITEMS], msk[ITEMS];
    float sum_sp = 0.f, sum_sc = 0.f, sum_m = 0.f;
    int first_open = INT_MAX;

    #pragma unroll
    for (int k = 0; k < ITEMS; k++) {
        const int j = k * BS + tid;
        float m = 0.f, spv = 0.f, scv = 0.f;
        if (j < U) {
            const float arv = anchor_src[base + j];
            m               = unit_mask[base + j];
            const float lrv = lr_unit[base + j];
            const float pwv = pw_unit[base + j];
            const float blv = bl_unit[base + j];
            const int   opv = open_run[base + j];
            const float a   = fmaxf(arv, 1.0f);
            const float b   = a * __expf(lrv);
            spv = fmaxf(fminf(b, a * 3.0f), 1.0f) * m;
            scv = fmaxf(pwv, 0.f) * (0.5f + blv) * m;
            if (opv > 0 && m > 0.f) first_open = min(first_open, j);
        }
        sp[k] = spv; sc[k] = scv; msk[k] = m;
        sum_sp += spv; sum_sc += scv; sum_m += m;
    }

    {
        float w0 = warpSum(sum_sp), w1 = warpSum(sum_sc), w2 = warpSum(sum_m);
        int w3 = warpMin(first_open);
        const int wid = tid >> 5, lid = tid & 31;
        if (lid == 0) { s_f0[wid] = w0; s_f1[wid] = w1; s_f2[wid] = w2; s_i0[wid] = w3; }
        __syncthreads();
        if (wid == 0) {
            float v0 = (lid < NW) ? s_f0[lid] : 0.f;
            float v1 = (lid < NW) ? s_f1[lid] : 0.f;
            float v2 = (lid < NW) ? s_f2[lid] : 0.f;
            int   v3 = (lid < NW) ? s_i0[lid] : INT_MAX;
            #pragma unroll
            for (int o = 8; o > 0; o >>= 1) {
                v0 += __shfl_down_sync(0xffffffffu, v0, o);
                v1 += __shfl_down_sync(0xffffffffu, v1, o);
                v2 += __shfl_down_sync(0xffffffffu, v2, o);
                v3 = min(v3, __shfl_down_sync(0xffffffffu, v3, o));
            }
            if (lid == 0) { s_bcast[0] = v0; s_bcast[1] = v1; s_bcast[2] = v2; s_ibcast = v3; }
        }
        __syncthreads();
        sum_sp = s_bcast[0]; sum_sc = s_bcast[1]; sum_m = s_bcast[2];
        first_open = s_ibcast;
    }

    const float sbud = speech_budget[row];
    const float pbud = pause_budget[row];
    const float speech_scale = sbud / fmaxf(sum_sp, 1e-6f);
    const int  visible  = (int)sum_m;
    const bool has_open = (first_open != INT_MAX);
    const int  closed   = has_open ? first_open : visible;
    const int  cap      = max(visible - 2, 0);
    int cand = min(cap, closed);
    const int prev = commit_frontier[row];
    const int bidx = min(max(cand - 1, 0), U - 1);
    const float bval = __ldg(bl_unit + base + bidx);
    const bool soft = (cand > 0) && (cand < visible) && (bval < 0.45f);
    if (soft) cand = max(prev, cand - 1);
    const int commit = max(prev, cand);

    const bool  use_scores = (sum_sc > 0.f);
    const float wdenom = 1.f / fmaxf(sum_sc, 1e-6f);
    const float fb     = 1.f / fmaxf(sum_m, 1.f);

    float sum_eff = 0.f, exec_s = 0.f, src_s = 0.f;
    #pragma unroll
    for (int k = 0; k < ITEMS; k++) {
        const int j = k * BS + tid;
        if (j < U) {
            const float speech = sp[k] * speech_scale;
            const float w      = use_scores ? (sc[k] * wdenom) : (msk[k] * fb);
            const float pause  = w * pbud;
            const float eff    = (speech + pause) * msk[k];
            out[base + j]          = speech;
            out[BU + base + j]     = pause;
            out[2 * BU + base + j] = eff;
            sum_eff += eff;
            if (j >= prev && j < commit) {
                exec_s += eff;
                src_s  += __ldg(anchor_src + base + j);
            }
        }
    }

    {
        float w0 = warpSum(sum_eff), w1 = warpSum(exec_s), w2 = warpSum(src_s);
        const int wid = tid >> 5, lid = tid & 31;
        __syncthreads();
        if (lid == 0) { s_f0[wid] = w0; s_f1[wid] = w1; s_f2[wid] = w2; }
        __syncthreads();
        if (tid == 0) {
            float v0 = 0.f, v1 = 0.f, v2 = 0.f;
            #pragma unroll
            for (int i = 0; i < NW; i++) { v0 += s_f0[i]; v1 += s_f1[i]; v2 += s_f2[i]; }
            const bool adv = commit > prev;
            const float cd = clock_delta[row];
            const float next_clock = adv ? (cd + (v1 - v2)) : cd;
            const float next_backlog = adv ? fmaxf(next_clock, 0.f) : backlog[row];
            const float vt = fmaxf(v0, 1.f);
            float next_phase = phase_ptr[row];
            if (adv) next_phase = fminf(fmaxf(next_phase + v1 / vt, 0.f), 1.f);
            float* tail = out + 3 * BU;
            tail[row]         = (float)commit;
            tail[B + row]     = next_phase;
            tail[2 * B + row] = next_backlog;
            tail[3 * B + row] = next_clock;
        }
    }
}

extern "C" void kernel_launch(void* const* d_in, const int* in_sizes, int n_in,
                              void* d_out, int out_size)
{
    const float* anchor_src  = (const float*)d_in[0];
    const float* unit_mask   = (const float*)d_in[1];
    const float* sbud        = (const float*)d_in[2];
    const float* pbud        = (const float*)d_in[3];
    const float* lr_unit     = (const float*)d_in[4];
    const float* pw_unit     = (const float*)d_in[5];
    const float* bl_unit     = (const float*)d_in[6];
    const float* phase_ptr   = (const float*)d_in[7];
    const float* backlog     = (const float*)d_in[8];
    const float* clock_delta = (const float*)d_in[9];
    const int*   frontier    = (const int*)d_in[10];
    const int*   open_run    = (const int*)d_in[11];
    float* out = (float*)d_out;

    const int B = in_sizes[2];            // speech_budget_win has B elements
    const int U = in_sizes[0] / B;        // dur_anchor_src has B*U

    if ((U & 3) == 0 && U <= BS * 4 && B <= MAX_ROWS) {
        const int preBlocks = (B + 7) / 8;        // 8 warps / 256-thread block
        precompute_row_stats<<<preBlocks, 256>>>(unit_mask, open_run, anchor_src,
                                                 bl_unit, frontier, B, U);
        rhythm_projector_v7<<<B, BS>>>(anchor_src, sbud, pbud, lr_unit, pw_unit,
            bl_unit, phase_ptr, backlog, clock_delta, frontier, out, B, U);
    } else {
        const int items = (U + BS - 1) / BS;
        dim3 grid(B), block(BS);
        #define LAUNCH(N) rhythm_projector_scalar<N><<<grid, block>>>(anchor_src,    \
            unit_mask, sbud, pbud, lr_unit, pw_unit, bl_unit, phase_ptr, backlog,    \
            clock_delta, frontier, open_run, out, B, U)
        if      (items <= 4)  LAUNCH(4);
        else if (items <= 8)  LAUNCH(8);
        else if (items <= 16) LAUNCH(16);
        else                  LAUNCH(32);
        #undef LAUNCH
    }
}